// round 12
// baseline (speedup 1.0000x reference)
#include <cuda_runtime.h>
#include <cuda_bf16.h>
#include <math.h>
#include <stdint.h>

#define NN 8192
#define DD 64

// ---------------- device scratch (allocation-free) ----------------
__device__ float g_rowsum[NN];
__device__ float g_colsum[NN];
__device__ float g_rinv[NN];
__device__ float g_cinv[NN];
__device__ __align__(16) __nv_bfloat16 g_adjbf[67108864];  // adj bf16 row-major
__device__ __align__(16) __nv_bfloat16 g_Qt[128 * NN];     // Q^T [n][k]
__device__ __align__(16) __nv_bfloat16 g_Pt[128 * NN];     // P^T [n][k]
__device__ __align__(16) float g_RiP[2][NN * 128];         // adj   @ Q split-K partials
__device__ __align__(16) float g_RuP[2][NN * 128];         // adj^T @ P split-K partials

__device__ __forceinline__ uint32_t smem_u32(const void* p) {
    uint32_t a;
    asm("{ .reg .u64 t; cvta.to.shared.u64 t, %1; cvt.u32.u64 %0, t; }" : "=r"(a) : "l"(p));
    return a;
}
__device__ __forceinline__ void cpa16(uint32_t s, const void* g) {
    asm volatile("cp.async.cg.shared.global [%0], [%1], 16;" :: "r"(s), "l"(g) : "memory");
}
__device__ __forceinline__ uint32_t bf2pk(float lo, float hi) {
    __nv_bfloat162 b = __float22bfloat162_rn(make_float2(lo, hi));
    return *(uint32_t*)&b;
}
__device__ __forceinline__ void mma_bf16(float* c, uint32_t a0, uint32_t a1, uint32_t a2,
                                         uint32_t a3, uint32_t b0, uint32_t b1) {
    asm volatile(
        "mma.sync.aligned.m16n8k16.row.col.f32.bf16.bf16.f32 "
        "{%0,%1,%2,%3}, {%4,%5,%6,%7}, {%8,%9}, {%0,%1,%2,%3};"
        : "+f"(c[0]), "+f"(c[1]), "+f"(c[2]), "+f"(c[3])
        : "r"(a0), "r"(a1), "r"(a2), "r"(a3), "r"(b0), "r"(b1));
}

// ---------------- 1) zero row+col sums ----------------
__global__ void zero_kernel() {
    int i = blockIdx.x * 256 + threadIdx.x;
    if (i < NN) { g_rowsum[i] = 0.f; g_colsum[i] = 0.f; }
}

// ---------------- 2) FUSED streaming convert fp32->bf16 + row/col sums ----------------
// grid (8, 32), 256 threads. Thread owns 4 consecutive cols, walks 256 rows
// (staggered per x-block to decorrelate same-row atomics). Pure register streaming:
// colsum in 4 regs, rowsum via warp shuffles. No smem, no syncs -> stays memory-bound.
__global__ void __launch_bounds__(256) convsum_kernel(const float* __restrict__ adj) {
    int tid = threadIdx.x;
    int lane = tid & 31;
    int c4 = (blockIdx.x * 256 + tid) * 4;
    int r0 = blockIdx.y * 256;
    int off = (blockIdx.x * 32) & 255;
    float s0 = 0.f, s1 = 0.f, s2 = 0.f, s3 = 0.f;
#pragma unroll 4
    for (int i = 0; i < 256; i++) {
        int r = r0 + ((i + off) & 255);
        float4 v = *(const float4*)&adj[(size_t)r * NN + c4];
        s0 += v.x; s1 += v.y; s2 += v.z; s3 += v.w;
        uint2 o;
        o.x = bf2pk(v.x, v.y);
        o.y = bf2pk(v.z, v.w);
        *(uint2*)&g_adjbf[(size_t)r * NN + c4] = o;
        float rs = (v.x + v.y) + (v.z + v.w);
        rs += __shfl_down_sync(0xffffffffu, rs, 16);
        rs += __shfl_down_sync(0xffffffffu, rs, 8);
        rs += __shfl_down_sync(0xffffffffu, rs, 4);
        rs += __shfl_down_sync(0xffffffffu, rs, 2);
        rs += __shfl_down_sync(0xffffffffu, rs, 1);
        if (lane == 0) atomicAdd(&g_rowsum[r], rs);
    }
    atomicAdd(&g_colsum[c4 + 0], s0);
    atomicAdd(&g_colsum[c4 + 1], s1);
    atomicAdd(&g_colsum[c4 + 2], s2);
    atomicAdd(&g_colsum[c4 + 3], s3);
}

// ---------------- 3) rinv / cinv ----------------
__global__ void scale_kernel() {
    int i = blockIdx.x * 256 + threadIdx.x;
    if (i < NN) {
        g_rinv[i] = rsqrtf(g_rowsum[i]);
        g_cinv[i] = rsqrtf(g_colsum[i]);
    }
}

// ---------------- 4) build Qt/Pt (bf16, [n][k]); 16 k-rows per block ----------------
__global__ void __launch_bounds__(256) prep_kernel(const float* __restrict__ user,
                                                   const float* __restrict__ item,
                                                   const float* __restrict__ W1) {
    int var = blockIdx.y;  // 0 -> Pt (src=item, scale=rinv), 1 -> Qt (src=user, scale=cinv)
    const float* src = var ? user : item;
    const float* pas = var ? item : user;
    const float* scl = var ? g_cinv : g_rinv;
    __nv_bfloat16* out = var ? g_Qt : g_Pt;

    __shared__ __align__(16) float Ws[DD * DD];
    __shared__ float Xs[16 * DD];
    __shared__ __nv_bfloat16 T[128 * 18];
    int tid = threadIdx.x;
    for (int i = tid; i < DD * DD; i += 256) Ws[i] = W1[i];
    int k0 = blockIdx.x * 16;
    for (int i = tid; i < 16 * DD; i += 256) Xs[i] = src[k0 * DD + i];
    __syncthreads();

    int row = tid >> 4;
    int g4 = (tid & 15) * 4;
    float a0 = 0.f, a1 = 0.f, a2 = 0.f, a3 = 0.f;
#pragma unroll 8
    for (int k = 0; k < DD; k++) {
        float x = Xs[row * DD + k];
        float4 w = *(const float4*)&Ws[k * DD + g4];
        a0 += x * w.x; a1 += x * w.y; a2 += x * w.z; a3 += x * w.w;
    }
    int gr = k0 + row;
    float s = scl[gr];
    T[(g4 + 0) * 18 + row] = __float2bfloat16(s * a0);
    T[(g4 + 1) * 18 + row] = __float2bfloat16(s * a1);
    T[(g4 + 2) * 18 + row] = __float2bfloat16(s * a2);
    T[(g4 + 3) * 18 + row] = __float2bfloat16(s * a3);
    const float* p = pas + gr * DD;
#pragma unroll
    for (int j = 0; j < 4; j++)
        T[(64 + g4 + j) * 18 + row] = __float2bfloat16(s * p[g4 + j]);
    __syncthreads();

    if (tid < 128) {
        int n = tid;
        __align__(16) __nv_bfloat16 v[16];
#pragma unroll
        for (int k = 0; k < 16; k++) v[k] = T[n * 18 + k];
        uint4* dst = (uint4*)(out + (size_t)n * NN + k0);
        dst[0] = ((uint4*)v)[0];
        dst[1] = ((uint4*)v)[1];
    }
}

// ---------------- 5) GEMMs: split-K=2, 3-stage pipeline, occupancy 2 ----------------
// grid (64, 2, 2); z = K-half. Tile 128x128, BK=64.
//  y=0: RiP[z][m-tile][128] = adjbf[m-tile][Khalf] @ Qt[:, Khalf]
//  y=1: RuT partial = Pt[:, Khalf] @ adjbf[Khalf][n-tile] -> transpose -> g_RuP[z][n][m]
// Stage = 16KB per operand; 3 stages x 2 operands = 96KB; 2 CTAs/SM = 192KB.
#define NST 3
#define ASTG 16384
#define NITER2 64
#define SMEM_GEMM (NST * 2 * ASTG)   // 98304 >= transpose 67584

__global__ void __launch_bounds__(256, 2) gemm_kernel() {
    extern __shared__ char sm[];
    uint32_t sA = smem_u32(sm);
    uint32_t sB = sA + NST * ASTG;

    int tid = threadIdx.x;
    int lane = tid & 31, wid = tid >> 5;
    int warpM = wid & 3, warpN = wid >> 2;  // 4x2 warps, warp tile 32m x 64n
    int z = blockIdx.z;
    size_t kbase = (size_t)z * 4096;        // K-half offset in elements

    float c[2][8][4];
#pragma unroll
    for (int f = 0; f < 2; f++)
#pragma unroll
        for (int n = 0; n < 8; n++)
#pragma unroll
            for (int j = 0; j < 4; j++) c[f][n][j] = 0.f;

    if (blockIdx.y == 0) {
        // ---------------- GEMM1: RiP[z] = adjbf @ Qt (K-half) ----------------
        int m0 = blockIdx.x * 128;
        float* Cg = g_RiP[z];
        int lr = tid >> 1, lc0 = (tid & 1) * 4;
        const char* gAp = (const char*)(g_adjbf + (size_t)(m0 + lr) * NN + kbase) + lc0 * 16;
        const char* gBp = (const char*)(g_Qt + (size_t)lr * NN + kbase) + lc0 * 16;
        uint32_t sto[4];
#pragma unroll
        for (int j = 0; j < 4; j++)
            sto[j] = lr * 128 + (((lc0 + j) ^ (lr & 7)) << 4);

        int aRow[2], aX[2];
#pragma unroll
        for (int f = 0; f < 2; f++) {
            aRow[f] = warpM * 32 + f * 16 + (lane & 15);
            aX[f] = aRow[f] & 7;
        }
        int ah = lane >> 4;
        int bRow[4], bX[4];
#pragma unroll
        for (int g = 0; g < 4; g++) {
            bRow[g] = warpN * 64 + g * 16 + (lane >> 4) * 8 + (lane & 7);
            bX[g] = bRow[g] & 7;
        }
        int bh = (lane >> 3) & 1;

        // prologue: stages 0, 1
#pragma unroll
        for (int s = 0; s < NST - 1; s++) {
#pragma unroll
            for (int j = 0; j < 4; j++) {
                cpa16(sA + s * ASTG + sto[j], gAp + (size_t)s * 128 + j * 16);
                cpa16(sB + s * ASTG + sto[j], gBp + (size_t)s * 128 + j * 16);
            }
            asm volatile("cp.async.commit_group;" ::: "memory");
        }

        for (int it = 0; it < NITER2; it++) {
            if (it <= NITER2 - 3) asm volatile("cp.async.wait_group 1;" ::: "memory");
            else                  asm volatile("cp.async.wait_group 0;" ::: "memory");
            __syncthreads();
            if (it + 2 < NITER2) {
                int s = (it + 2) % NST;
                size_t kb = (size_t)(it + 2) * 128;
#pragma unroll
                for (int j = 0; j < 4; j++) {
                    cpa16(sA + s * ASTG + sto[j], gAp + kb + j * 16);
                    cpa16(sB + s * ASTG + sto[j], gBp + kb + j * 16);
                }
                asm volatile("cp.async.commit_group;" ::: "memory");
            }
            uint32_t ba = sA + (it % NST) * ASTG;
            uint32_t bb = sB + (it % NST) * ASTG;
#pragma unroll
            for (int ks = 0; ks < 4; ks++) {
                uint32_t am[2][4], bn[4][4];
#pragma unroll
                for (int f = 0; f < 2; f++) {
                    uint32_t addr = ba + aRow[f] * 128 + ((((ks << 1) | ah) ^ aX[f]) << 4);
                    asm volatile("ldmatrix.sync.aligned.m8n8.x4.shared.b16 {%0,%1,%2,%3}, [%4];"
                                 : "=r"(am[f][0]), "=r"(am[f][1]), "=r"(am[f][2]), "=r"(am[f][3])
                                 : "r"(addr));
                }
#pragma unroll
                for (int g = 0; g < 4; g++) {
                    uint32_t addr = bb + bRow[g] * 128 + ((((ks << 1) | bh) ^ bX[g]) << 4);
                    asm volatile("ldmatrix.sync.aligned.m8n8.x4.shared.b16 {%0,%1,%2,%3}, [%4];"
                                 : "=r"(bn[g][0]), "=r"(bn[g][1]), "=r"(bn[g][2]), "=r"(bn[g][3])
                                 : "r"(addr));
                }
#pragma unroll
                for (int f = 0; f < 2; f++)
#pragma unroll
                    for (int g = 0; g < 4; g++) {
                        mma_bf16(c[f][g * 2], am[f][0], am[f][1], am[f][2], am[f][3],
                                 bn[g][0], bn[g][1]);
                        mma_bf16(c[f][g * 2 + 1], am[f][0], am[f][1], am[f][2], am[f][3],
                                 bn[g][2], bn[g][3]);
                    }
            }
        }
#pragma unroll
        for (int f = 0; f < 2; f++) {
            int row = m0 + warpM * 32 + f * 16 + (lane >> 2);
#pragma unroll
            for (int n = 0; n < 8; n++) {
                int col = warpN * 64 + n * 8 + (lane & 3) * 2;
                *(float2*)&Cg[(size_t)row * 128 + col] = make_float2(c[f][n][0], c[f][n][1]);
                *(float2*)&Cg[(size_t)(row + 8) * 128 + col] = make_float2(c[f][n][2], c[f][n][3]);
            }
        }
    } else {
        // ---------------- GEMM2: RuT partial = Pt @ adjbf[Khalf, n-tile] ----------------
        int n0 = blockIdx.x * 128;
        float* Cg = g_RuP[z];
        int lrA = tid >> 1, lcA = (tid & 1) * 4;
        const char* gAp = (const char*)(g_Pt + (size_t)lrA * NN + kbase) + lcA * 16;
        uint32_t stoA[4];
#pragma unroll
        for (int j = 0; j < 4; j++)
            stoA[j] = lrA * 128 + (((lcA + j) ^ (lrA & 7)) << 4);

        int lrB = tid >> 2, lcB = (tid & 3) * 4;
        const char* gBp = (const char*)(g_adjbf + (size_t)(kbase + lrB) * NN + n0) + lcB * 16;
        uint32_t stoB[4];
#pragma unroll
        for (int j = 0; j < 4; j++)
            stoB[j] = lrB * 256 + (((lcB + j) ^ (lrB & 7)) << 4);

        int aRow[2], aX[2];
#pragma unroll
        for (int f = 0; f < 2; f++) {
            aRow[f] = warpM * 32 + f * 16 + (lane & 15);
            aX[f] = aRow[f] & 7;
        }
        int ah = lane >> 4;
        int srow0 = ((lane >> 4) & 1) * 8 + (lane & 7);
        int scb = (lane >> 3) & 1;

        // prologue: stages 0, 1
#pragma unroll
        for (int s = 0; s < NST - 1; s++) {
#pragma unroll
            for (int j = 0; j < 4; j++) {
                cpa16(sA + s * ASTG + stoA[j], gAp + (size_t)s * 128 + j * 16);
                cpa16(sB + s * ASTG + stoB[j], gBp + (size_t)s * 64 * NN * 2 + j * 16);
            }
            asm volatile("cp.async.commit_group;" ::: "memory");
        }

        for (int it = 0; it < NITER2; it++) {
            if (it <= NITER2 - 3) asm volatile("cp.async.wait_group 1;" ::: "memory");
            else                  asm volatile("cp.async.wait_group 0;" ::: "memory");
            __syncthreads();
            if (it + 2 < NITER2) {
                int s = (it + 2) % NST;
                size_t kit = (size_t)(it + 2);
#pragma unroll
                for (int j = 0; j < 4; j++) {
                    cpa16(sA + s * ASTG + stoA[j], gAp + kit * 128 + j * 16);
                    cpa16(sB + s * ASTG + stoB[j], gBp + kit * 64 * NN * 2 + j * 16);
                }
                asm volatile("cp.async.commit_group;" ::: "memory");
            }
            uint32_t ba = sA + (it % NST) * ASTG;
            uint32_t bb = sB + (it % NST) * ASTG;
#pragma unroll
            for (int ks = 0; ks < 4; ks++) {
                uint32_t am[2][4], bn[4][4];
#pragma unroll
                for (int f = 0; f < 2; f++) {
                    uint32_t addr = ba + aRow[f] * 128 + ((((ks << 1) | ah) ^ aX[f]) << 4);
                    asm volatile("ldmatrix.sync.aligned.m8n8.x4.shared.b16 {%0,%1,%2,%3}, [%4];"
                                 : "=r"(am[f][0]), "=r"(am[f][1]), "=r"(am[f][2]), "=r"(am[f][3])
                                 : "r"(addr));
                }
                int srow = ks * 16 + srow0;
                int sxr = srow & 7;
#pragma unroll
                for (int g = 0; g < 4; g++) {
                    int sc = warpN * 8 + g * 2 + scb;
                    uint32_t addr = bb + srow * 256 + ((sc ^ sxr) << 4);
                    asm volatile("ldmatrix.sync.aligned.m8n8.x4.trans.shared.b16 {%0,%1,%2,%3}, [%4];"
                                 : "=r"(bn[g][0]), "=r"(bn[g][1]), "=r"(bn[g][2]), "=r"(bn[g][3])
                                 : "r"(addr));
                }
#pragma unroll
                for (int f = 0; f < 2; f++)
#pragma unroll
                    for (int g = 0; g < 4; g++) {
                        mma_bf16(c[f][g * 2], am[f][0], am[f][1], am[f][2], am[f][3],
                                 bn[g][0], bn[g][2]);
                        mma_bf16(c[f][g * 2 + 1], am[f][0], am[f][1], am[f][2], am[f][3],
                                 bn[g][1], bn[g][3]);
                    }
            }
        }

        // transpose epilogue: smem [128n][132] fp32, then coalesced rows of partial Ru
        __syncthreads();
        float* tr = (float*)sm;
#pragma unroll
        for (int f = 0; f < 2; f++) {
            int m = warpM * 32 + f * 16 + (lane >> 2);
#pragma unroll
            for (int n = 0; n < 8; n++) {
                int nc = warpN * 64 + n * 8 + (lane & 3) * 2;
                tr[nc * 132 + m] = c[f][n][0];
                tr[(nc + 1) * 132 + m] = c[f][n][1];
                tr[nc * 132 + m + 8] = c[f][n][2];
                tr[(nc + 1) * 132 + m + 8] = c[f][n][3];
            }
        }
        __syncthreads();
        for (int i = tid; i < 128 * 32; i += 256) {
            int r = i >> 5, q = i & 31;
            float4 v = *(float4*)&tr[r * 132 + q * 4];
            *(float4*)&Cg[(size_t)(n0 + r) * 128 + q * 4] = v;
        }
    }
}

// ---------------- 6) epilogue (sums split-K partials) ----------------
__global__ void __launch_bounds__(256) final_kernel(const float* __restrict__ user,
                                                    const float* __restrict__ item,
                                                    const float* __restrict__ W2,
                                                    float* __restrict__ out) {
    int var = blockIdx.y;  // 0 -> updated_user (Ru, cinv), 1 -> updated_item (Ri, rinv)
    const float* R0 = var ? g_RiP[0] : g_RuP[0];
    const float* R1 = var ? g_RiP[1] : g_RuP[1];
    const float* scl = var ? g_rinv : g_cinv;
    const float* src = var ? user : item;
    const float* tgt = var ? item : user;
    float* o = out + (size_t)var * NN * DD;

    __shared__ __align__(16) float Ws[DD * DD];
    __shared__ float Hs[16 * DD];
    int tid = threadIdx.x;
    for (int i = tid; i < DD * DD; i += 256) Ws[i] = W2[i];

    int r0 = blockIdx.x * 16;
    int row = tid >> 4;
    int cg = (tid & 15) * 4;
    int gr = r0 + row;
    float s = scl[gr];
#pragma unroll
    for (int j = 0; j < 4; j++) {
        float rv = R0[gr * 128 + 64 + cg + j] + R1[gr * 128 + 64 + cg + j];
        Hs[row * DD + cg + j] = src[gr * DD + cg + j] * (s * rv);
    }
    __syncthreads();

    float acc[4] = {0.f, 0.f, 0.f, 0.f};
#pragma unroll 8
    for (int k = 0; k < DD; k++) {
        float hh = Hs[row * DD + k];
        float4 w = *(const float4*)&Ws[k * DD + cg];
        acc[0] += hh * w.x; acc[1] += hh * w.y; acc[2] += hh * w.z; acc[3] += hh * w.w;
    }
#pragma unroll
    for (int j = 0; j < 4; j++) {
        float rv = R0[gr * 128 + cg + j] + R1[gr * 128 + cg + j];
        float x = s * rv + acc[j] + tgt[gr * DD + cg + j];
        o[gr * DD + cg + j] = x > 0.f ? x : 0.2f * x;
    }
}

// ---------------- launch ----------------
extern "C" void kernel_launch(void* const* d_in, const int* in_sizes, int n_in,
                              void* d_out, int out_size) {
    const float* user = (const float*)d_in[0];
    const float* item = (const float*)d_in[1];
    const float* adj  = (const float*)d_in[2];
    const float* W1   = (const float*)d_in[3];
    const float* W2   = (const float*)d_in[4];
    float* out = (float*)d_out;

    cudaFuncSetAttribute(gemm_kernel, cudaFuncAttributeMaxDynamicSharedMemorySize, SMEM_GEMM);

    zero_kernel<<<32, 256>>>();
    convsum_kernel<<<dim3(8, 32), 256>>>(adj);
    scale_kernel<<<32, 256>>>();
    prep_kernel<<<dim3(512, 2), 256>>>(user, item, W1);
    gemm_kernel<<<dim3(64, 2, 2), 256, SMEM_GEMM>>>();
    final_kernel<<<dim3(512, 2), 256>>>(user, item, W2, out);
}

// round 13
// speedup vs baseline: 1.2253x; 1.2253x over previous
#include <cuda_runtime.h>
#include <cuda_bf16.h>
#include <math.h>
#include <stdint.h>

#define NN 8192
#define DD 64
#define ONES 0x3F803F80u

// ---------------- device scratch (allocation-free) ----------------
__device__ float g_rowsum[NN];
__device__ float g_colsum[NN];
__device__ float g_rinv[NN];
__device__ float g_cinv[NN];
__device__ __align__(16) __nv_bfloat16 g_adjbf[67108864];  // adj bf16 row-major
__device__ __align__(16) __nv_bfloat16 g_Qt[128 * NN];     // Q^T [n][k]
__device__ __align__(16) __nv_bfloat16 g_Pt[128 * NN];     // P^T [n][k]
__device__ __align__(16) float g_RiP[2][NN * 128];         // adj   @ Q split-K partials
__device__ __align__(16) float g_RuP[2][NN * 128];         // adj^T @ P split-K partials

__device__ __forceinline__ uint32_t smem_u32(const void* p) {
    uint32_t a;
    asm("{ .reg .u64 t; cvta.to.shared.u64 t, %1; cvt.u32.u64 %0, t; }" : "=r"(a) : "l"(p));
    return a;
}
__device__ __forceinline__ void cpa16(uint32_t s, const void* g) {
    asm volatile("cp.async.cg.shared.global [%0], [%1], 16;" :: "r"(s), "l"(g) : "memory");
}
__device__ __forceinline__ uint32_t bf2pk(float lo, float hi) {
    __nv_bfloat162 b = __float22bfloat162_rn(make_float2(lo, hi));
    return *(uint32_t*)&b;
}
__device__ __forceinline__ void mma_bf16(float* c, uint32_t a0, uint32_t a1, uint32_t a2,
                                         uint32_t a3, uint32_t b0, uint32_t b1) {
    asm volatile(
        "mma.sync.aligned.m16n8k16.row.col.f32.bf16.bf16.f32 "
        "{%0,%1,%2,%3}, {%4,%5,%6,%7}, {%8,%9}, {%0,%1,%2,%3};"
        : "+f"(c[0]), "+f"(c[1]), "+f"(c[2]), "+f"(c[3])
        : "r"(a0), "r"(a1), "r"(a2), "r"(a3), "r"(b0), "r"(b1));
}

// ---------------- 1) zero colsum ----------------
__global__ void zero_kernel() {
    int i = blockIdx.x * 256 + threadIdx.x;
    if (i < NN) g_colsum[i] = 0.f;
}

// ---------------- 2) pure streaming convert fp32 -> bf16 ----------------
__global__ void __launch_bounds__(256) convert_kernel(const float* __restrict__ adj) {
    int gid = blockIdx.x * 256 + threadIdx.x;
    const int NF4 = NN * NN / 4;
    const int STR = gridDim.x * 256;
    for (int i = gid; i < NF4; i += STR) {
        float4 v = ((const float4*)adj)[i];
        uint2 o;
        o.x = bf2pk(v.x, v.y);
        o.y = bf2pk(v.z, v.w);
        ((uint2*)g_adjbf)[i] = o;
    }
}

// ---------------- 3) tensor-core row/col sums of adjbf ----------------
#define SROWS 64
#define SCOLS 128
__global__ void __launch_bounds__(256) sums_kernel() {
    __shared__ __align__(16) __nv_bfloat16 st[3][SROWS * SCOLS];
    int tid = threadIdx.x, lane = tid & 31, wid = tid >> 5;
    int r0 = blockIdx.x * SROWS;

    int lr = tid >> 2, lc0 = (tid & 3) * 4;
    const char* gp = (const char*)(g_adjbf + (size_t)(r0 + lr) * NN) + lc0 * 16;
    uint32_t sbase = smem_u32(st);
    uint32_t sto[4];
#pragma unroll
    for (int j = 0; j < 4; j++)
        sto[j] = lr * 256 + (((lc0 + j) ^ (lr & 7)) << 4);

#pragma unroll
    for (int s = 0; s < 2; s++) {
#pragma unroll
        for (int j = 0; j < 4; j++)
            cpa16(sbase + s * (SROWS * SCOLS * 2) + sto[j], gp + (size_t)s * 256 + j * 16);
        asm volatile("cp.async.commit_group;" ::: "memory");
    }

    float rc[4] = {0.f, 0.f, 0.f, 0.f};

    for (int it = 0; it < 64; it++) {
        if (it < 62) asm volatile("cp.async.wait_group 1;" ::: "memory");
        else         asm volatile("cp.async.wait_group 0;" ::: "memory");
        __syncthreads();
        if (it + 2 < 64) {
            int s = (it + 2) % 3;
#pragma unroll
            for (int j = 0; j < 4; j++)
                cpa16(sbase + s * (SROWS * SCOLS * 2) + sto[j],
                      gp + (size_t)(it + 2) * 256 + j * 16);
            asm volatile("cp.async.commit_group;" ::: "memory");
        }
        uint32_t buf = sbase + (it % 3) * (SROWS * SCOLS * 2);

        if (wid < 4) {
            int aRow = wid * 16 + (lane & 15);
            int ax = aRow & 7;
#pragma unroll
            for (int kc = 0; kc < 8; kc++) {
                uint32_t a0, a1, a2, a3;
                uint32_t addr = buf + aRow * 256 + ((((kc << 1) | (lane >> 4)) ^ ax) << 4);
                asm volatile("ldmatrix.sync.aligned.m8n8.x4.shared.b16 {%0,%1,%2,%3}, [%4];"
                             : "=r"(a0), "=r"(a1), "=r"(a2), "=r"(a3) : "r"(addr));
                mma_bf16(rc, a0, a1, a2, a3, ONES, ONES);
            }
        }

        float cc0[4] = {0.f, 0.f, 0.f, 0.f}, cc1[4] = {0.f, 0.f, 0.f, 0.f};
        int srow0 = ((lane >> 4) & 1) * 8 + (lane & 7);
        int sc = wid * 2 + ((lane >> 3) & 1);
#pragma unroll
        for (int kc = 0; kc < 4; kc++) {
            int srow = kc * 16 + srow0;
            uint32_t b0, b1, b2, b3;
            uint32_t addr = buf + srow * 256 + ((sc ^ (srow & 7)) << 4);
            asm volatile("ldmatrix.sync.aligned.m8n8.x4.trans.shared.b16 {%0,%1,%2,%3}, [%4];"
                         : "=r"(b0), "=r"(b1), "=r"(b2), "=r"(b3) : "r"(addr));
            mma_bf16(cc0, ONES, ONES, ONES, ONES, b0, b2);
            mma_bf16(cc1, ONES, ONES, ONES, ONES, b1, b3);
        }
        if (lane < 4) {
            int colb = it * 128 + wid * 16 + 2 * lane;
            atomicAdd(&g_colsum[colb + 0], cc0[0]);
            atomicAdd(&g_colsum[colb + 1], cc0[1]);
            atomicAdd(&g_colsum[colb + 8], cc1[0]);
            atomicAdd(&g_colsum[colb + 9], cc1[1]);
        }
    }

    if (wid < 4 && (lane & 3) == 0) {
        int row = r0 + wid * 16 + (lane >> 2);
        g_rowsum[row] = rc[0];
        g_rowsum[row + 8] = rc[2];
    }
}

// ---------------- 4) rinv / cinv ----------------
__global__ void scale_kernel() {
    int i = blockIdx.x * 256 + threadIdx.x;
    if (i < NN) {
        g_rinv[i] = rsqrtf(g_rowsum[i]);
        g_cinv[i] = rsqrtf(g_colsum[i]);
    }
}

// ---------------- 5) build Qt/Pt (bf16, [n][k]); 16 k-rows per block ----------------
__global__ void __launch_bounds__(256) prep_kernel(const float* __restrict__ user,
                                                   const float* __restrict__ item,
                                                   const float* __restrict__ W1) {
    int var = blockIdx.y;  // 0 -> Pt (src=item, scale=rinv), 1 -> Qt (src=user, scale=cinv)
    const float* src = var ? user : item;
    const float* pas = var ? item : user;
    const float* scl = var ? g_cinv : g_rinv;
    __nv_bfloat16* out = var ? g_Qt : g_Pt;

    __shared__ __align__(16) float Ws[DD * DD];
    __shared__ float Xs[16 * DD];
    __shared__ __nv_bfloat16 T[128 * 18];
    int tid = threadIdx.x;
    for (int i = tid; i < DD * DD; i += 256) Ws[i] = W1[i];
    int k0 = blockIdx.x * 16;
    for (int i = tid; i < 16 * DD; i += 256) Xs[i] = src[k0 * DD + i];
    __syncthreads();

    int row = tid >> 4;
    int g4 = (tid & 15) * 4;
    float a0 = 0.f, a1 = 0.f, a2 = 0.f, a3 = 0.f;
#pragma unroll 8
    for (int k = 0; k < DD; k++) {
        float x = Xs[row * DD + k];
        float4 w = *(const float4*)&Ws[k * DD + g4];
        a0 += x * w.x; a1 += x * w.y; a2 += x * w.z; a3 += x * w.w;
    }
    int gr = k0 + row;
    float s = scl[gr];
    T[(g4 + 0) * 18 + row] = __float2bfloat16(s * a0);
    T[(g4 + 1) * 18 + row] = __float2bfloat16(s * a1);
    T[(g4 + 2) * 18 + row] = __float2bfloat16(s * a2);
    T[(g4 + 3) * 18 + row] = __float2bfloat16(s * a3);
    const float* p = pas + gr * DD;
#pragma unroll
    for (int j = 0; j < 4; j++)
        T[(64 + g4 + j) * 18 + row] = __float2bfloat16(s * p[g4 + j]);
    __syncthreads();

    if (tid < 128) {
        int n = tid;
        __align__(16) __nv_bfloat16 v[16];
#pragma unroll
        for (int k = 0; k < 16; k++) v[k] = T[n * 18 + k];
        uint4* dst = (uint4*)(out + (size_t)n * NN + k0);
        dst[0] = ((uint4*)v)[0];
        dst[1] = ((uint4*)v)[1];
    }
}

// ---------------- 6) GEMMs: split-K=2, 3-stage pipeline, occupancy 2 ----------------
// grid (64, 2, 2); z = K-half. Tile 128x128, BK=64.
//  y=0: RiP[z][m-tile][128] = adjbf[m-tile][Khalf] @ Qt[:, Khalf]
//  y=1: RuT partial = Pt[:, Khalf] @ adjbf[Khalf][n-tile] -> transpose -> g_RuP[z][n][m]
// Stage = 16KB per operand; 3 stages x 2 operands = 96KB; 2 CTAs/SM = 192KB.
#define NST 3
#define ASTG 16384
#define NITER2 64
#define SMEM_GEMM (NST * 2 * ASTG)   // 98304 >= transpose 67584

__global__ void __launch_bounds__(256, 2) gemm_kernel() {
    extern __shared__ char sm[];
    uint32_t sA = smem_u32(sm);
    uint32_t sB = sA + NST * ASTG;

    int tid = threadIdx.x;
    int lane = tid & 31, wid = tid >> 5;
    int warpM = wid & 3, warpN = wid >> 2;  // 4x2 warps, warp tile 32m x 64n
    int z = blockIdx.z;
    size_t kbase = (size_t)z * 4096;        // K-half offset in elements

    float c[2][8][4];
#pragma unroll
    for (int f = 0; f < 2; f++)
#pragma unroll
        for (int n = 0; n < 8; n++)
#pragma unroll
            for (int j = 0; j < 4; j++) c[f][n][j] = 0.f;

    if (blockIdx.y == 0) {
        // ---------------- GEMM1: RiP[z] = adjbf @ Qt (K-half) ----------------
        int m0 = blockIdx.x * 128;
        float* Cg = g_RiP[z];
        int lr = tid >> 1, lc0 = (tid & 1) * 4;
        const char* gAp = (const char*)(g_adjbf + (size_t)(m0 + lr) * NN + kbase) + lc0 * 16;
        const char* gBp = (const char*)(g_Qt + (size_t)lr * NN + kbase) + lc0 * 16;
        uint32_t sto[4];
#pragma unroll
        for (int j = 0; j < 4; j++)
            sto[j] = lr * 128 + (((lc0 + j) ^ (lr & 7)) << 4);

        int aRow[2], aX[2];
#pragma unroll
        for (int f = 0; f < 2; f++) {
            aRow[f] = warpM * 32 + f * 16 + (lane & 15);
            aX[f] = aRow[f] & 7;
        }
        int ah = lane >> 4;
        int bRow[4], bX[4];
#pragma unroll
        for (int g = 0; g < 4; g++) {
            bRow[g] = warpN * 64 + g * 16 + (lane >> 4) * 8 + (lane & 7);
            bX[g] = bRow[g] & 7;
        }
        int bh = (lane >> 3) & 1;

        // prologue: stages 0, 1
#pragma unroll
        for (int s = 0; s < NST - 1; s++) {
#pragma unroll
            for (int j = 0; j < 4; j++) {
                cpa16(sA + s * ASTG + sto[j], gAp + (size_t)s * 128 + j * 16);
                cpa16(sB + s * ASTG + sto[j], gBp + (size_t)s * 128 + j * 16);
            }
            asm volatile("cp.async.commit_group;" ::: "memory");
        }

        for (int it = 0; it < NITER2; it++) {
            if (it <= NITER2 - 3) asm volatile("cp.async.wait_group 1;" ::: "memory");
            else                  asm volatile("cp.async.wait_group 0;" ::: "memory");
            __syncthreads();
            if (it + 2 < NITER2) {
                int s = (it + 2) % NST;
                size_t kb = (size_t)(it + 2) * 128;
#pragma unroll
                for (int j = 0; j < 4; j++) {
                    cpa16(sA + s * ASTG + sto[j], gAp + kb + j * 16);
                    cpa16(sB + s * ASTG + sto[j], gBp + kb + j * 16);
                }
                asm volatile("cp.async.commit_group;" ::: "memory");
            }
            uint32_t ba = sA + (it % NST) * ASTG;
            uint32_t bb = sB + (it % NST) * ASTG;
#pragma unroll
            for (int ks = 0; ks < 4; ks++) {
                uint32_t am[2][4], bn[4][4];
#pragma unroll
                for (int f = 0; f < 2; f++) {
                    uint32_t addr = ba + aRow[f] * 128 + ((((ks << 1) | ah) ^ aX[f]) << 4);
                    asm volatile("ldmatrix.sync.aligned.m8n8.x4.shared.b16 {%0,%1,%2,%3}, [%4];"
                                 : "=r"(am[f][0]), "=r"(am[f][1]), "=r"(am[f][2]), "=r"(am[f][3])
                                 : "r"(addr));
                }
#pragma unroll
                for (int g = 0; g < 4; g++) {
                    uint32_t addr = bb + bRow[g] * 128 + ((((ks << 1) | bh) ^ bX[g]) << 4);
                    asm volatile("ldmatrix.sync.aligned.m8n8.x4.shared.b16 {%0,%1,%2,%3}, [%4];"
                                 : "=r"(bn[g][0]), "=r"(bn[g][1]), "=r"(bn[g][2]), "=r"(bn[g][3])
                                 : "r"(addr));
                }
#pragma unroll
                for (int f = 0; f < 2; f++)
#pragma unroll
                    for (int g = 0; g < 4; g++) {
                        mma_bf16(c[f][g * 2], am[f][0], am[f][1], am[f][2], am[f][3],
                                 bn[g][0], bn[g][1]);
                        mma_bf16(c[f][g * 2 + 1], am[f][0], am[f][1], am[f][2], am[f][3],
                                 bn[g][2], bn[g][3]);
                    }
            }
        }
#pragma unroll
        for (int f = 0; f < 2; f++) {
            int row = m0 + warpM * 32 + f * 16 + (lane >> 2);
#pragma unroll
            for (int n = 0; n < 8; n++) {
                int col = warpN * 64 + n * 8 + (lane & 3) * 2;
                *(float2*)&Cg[(size_t)row * 128 + col] = make_float2(c[f][n][0], c[f][n][1]);
                *(float2*)&Cg[(size_t)(row + 8) * 128 + col] = make_float2(c[f][n][2], c[f][n][3]);
            }
        }
    } else {
        // ---------------- GEMM2: RuT partial = Pt @ adjbf[Khalf, n-tile] ----------------
        int n0 = blockIdx.x * 128;
        float* Cg = g_RuP[z];
        int lrA = tid >> 1, lcA = (tid & 1) * 4;
        const char* gAp = (const char*)(g_Pt + (size_t)lrA * NN + kbase) + lcA * 16;
        uint32_t stoA[4];
#pragma unroll
        for (int j = 0; j < 4; j++)
            stoA[j] = lrA * 128 + (((lcA + j) ^ (lrA & 7)) << 4);

        int lrB = tid >> 2, lcB = (tid & 3) * 4;
        const char* gBp = (const char*)(g_adjbf + (size_t)(kbase + lrB) * NN + n0) + lcB * 16;
        uint32_t stoB[4];
#pragma unroll
        for (int j = 0; j < 4; j++)
            stoB[j] = lrB * 256 + (((lcB + j) ^ (lrB & 7)) << 4);

        int aRow[2], aX[2];
#pragma unroll
        for (int f = 0; f < 2; f++) {
            aRow[f] = warpM * 32 + f * 16 + (lane & 15);
            aX[f] = aRow[f] & 7;
        }
        int ah = lane >> 4;
        int srow0 = ((lane >> 4) & 1) * 8 + (lane & 7);
        int scb = (lane >> 3) & 1;

        // prologue: stages 0, 1
#pragma unroll
        for (int s = 0; s < NST - 1; s++) {
#pragma unroll
            for (int j = 0; j < 4; j++) {
                cpa16(sA + s * ASTG + stoA[j], gAp + (size_t)s * 128 + j * 16);
                cpa16(sB + s * ASTG + stoB[j], gBp + (size_t)s * 64 * NN * 2 + j * 16);
            }
            asm volatile("cp.async.commit_group;" ::: "memory");
        }

        for (int it = 0; it < NITER2; it++) {
            if (it <= NITER2 - 3) asm volatile("cp.async.wait_group 1;" ::: "memory");
            else                  asm volatile("cp.async.wait_group 0;" ::: "memory");
            __syncthreads();
            if (it + 2 < NITER2) {
                int s = (it + 2) % NST;
                size_t kit = (size_t)(it + 2);
#pragma unroll
                for (int j = 0; j < 4; j++) {
                    cpa16(sA + s * ASTG + stoA[j], gAp + kit * 128 + j * 16);
                    cpa16(sB + s * ASTG + stoB[j], gBp + kit * 64 * NN * 2 + j * 16);
                }
                asm volatile("cp.async.commit_group;" ::: "memory");
            }
            uint32_t ba = sA + (it % NST) * ASTG;
            uint32_t bb = sB + (it % NST) * ASTG;
#pragma unroll
            for (int ks = 0; ks < 4; ks++) {
                uint32_t am[2][4], bn[4][4];
#pragma unroll
                for (int f = 0; f < 2; f++) {
                    uint32_t addr = ba + aRow[f] * 128 + ((((ks << 1) | ah) ^ aX[f]) << 4);
                    asm volatile("ldmatrix.sync.aligned.m8n8.x4.shared.b16 {%0,%1,%2,%3}, [%4];"
                                 : "=r"(am[f][0]), "=r"(am[f][1]), "=r"(am[f][2]), "=r"(am[f][3])
                                 : "r"(addr));
                }
                int srow = ks * 16 + srow0;
                int sxr = srow & 7;
#pragma unroll
                for (int g = 0; g < 4; g++) {
                    int sc = warpN * 8 + g * 2 + scb;
                    uint32_t addr = bb + srow * 256 + ((sc ^ sxr) << 4);
                    asm volatile("ldmatrix.sync.aligned.m8n8.x4.trans.shared.b16 {%0,%1,%2,%3}, [%4];"
                                 : "=r"(bn[g][0]), "=r"(bn[g][1]), "=r"(bn[g][2]), "=r"(bn[g][3])
                                 : "r"(addr));
                }
#pragma unroll
                for (int f = 0; f < 2; f++)
#pragma unroll
                    for (int g = 0; g < 4; g++) {
                        mma_bf16(c[f][g * 2], am[f][0], am[f][1], am[f][2], am[f][3],
                                 bn[g][0], bn[g][2]);
                        mma_bf16(c[f][g * 2 + 1], am[f][0], am[f][1], am[f][2], am[f][3],
                                 bn[g][1], bn[g][3]);
                    }
            }
        }

        // transpose epilogue: smem [128n][132] fp32, then coalesced rows of partial Ru
        __syncthreads();
        float* tr = (float*)sm;
#pragma unroll
        for (int f = 0; f < 2; f++) {
            int m = warpM * 32 + f * 16 + (lane >> 2);
#pragma unroll
            for (int n = 0; n < 8; n++) {
                int nc = warpN * 64 + n * 8 + (lane & 3) * 2;
                tr[nc * 132 + m] = c[f][n][0];
                tr[(nc + 1) * 132 + m] = c[f][n][1];
                tr[nc * 132 + m + 8] = c[f][n][2];
                tr[(nc + 1) * 132 + m + 8] = c[f][n][3];
            }
        }
        __syncthreads();
        for (int i = tid; i < 128 * 32; i += 256) {
            int r = i >> 5, q = i & 31;
            float4 v = *(float4*)&tr[r * 132 + q * 4];
            *(float4*)&Cg[(size_t)(n0 + r) * 128 + q * 4] = v;
        }
    }
}

// ---------------- 7) epilogue (sums split-K partials) ----------------
__global__ void __launch_bounds__(256) final_kernel(const float* __restrict__ user,
                                                    const float* __restrict__ item,
                                                    const float* __restrict__ W2,
                                                    float* __restrict__ out) {
    int var = blockIdx.y;  // 0 -> updated_user (Ru, cinv), 1 -> updated_item (Ri, rinv)
    const float* R0 = var ? g_RiP[0] : g_RuP[0];
    const float* R1 = var ? g_RiP[1] : g_RuP[1];
    const float* scl = var ? g_rinv : g_cinv;
    const float* src = var ? user : item;
    const float* tgt = var ? item : user;
    float* o = out + (size_t)var * NN * DD;

    __shared__ __align__(16) float Ws[DD * DD];
    __shared__ float Hs[16 * DD];
    int tid = threadIdx.x;
    for (int i = tid; i < DD * DD; i += 256) Ws[i] = W2[i];

    int r0 = blockIdx.x * 16;
    int row = tid >> 4;
    int cg = (tid & 15) * 4;
    int gr = r0 + row;
    float s = scl[gr];
#pragma unroll
    for (int j = 0; j < 4; j++) {
        float rv = R0[gr * 128 + 64 + cg + j] + R1[gr * 128 + 64 + cg + j];
        Hs[row * DD + cg + j] = src[gr * DD + cg + j] * (s * rv);
    }
    __syncthreads();

    float acc[4] = {0.f, 0.f, 0.f, 0.f};
#pragma unroll 8
    for (int k = 0; k < DD; k++) {
        float hh = Hs[row * DD + k];
        float4 w = *(const float4*)&Ws[k * DD + cg];
        acc[0] += hh * w.x; acc[1] += hh * w.y; acc[2] += hh * w.z; acc[3] += hh * w.w;
    }
#pragma unroll
    for (int j = 0; j < 4; j++) {
        float rv = R0[gr * 128 + cg + j] + R1[gr * 128 + cg + j];
        float x = s * rv + acc[j] + tgt[gr * DD + cg + j];
        o[gr * DD + cg + j] = x > 0.f ? x : 0.2f * x;
    }
}

// ---------------- launch ----------------
extern "C" void kernel_launch(void* const* d_in, const int* in_sizes, int n_in,
                              void* d_out, int out_size) {
    const float* user = (const float*)d_in[0];
    const float* item = (const float*)d_in[1];
    const float* adj  = (const float*)d_in[2];
    const float* W1   = (const float*)d_in[3];
    const float* W2   = (const float*)d_in[4];
    float* out = (float*)d_out;

    cudaFuncSetAttribute(gemm_kernel, cudaFuncAttributeMaxDynamicSharedMemorySize, SMEM_GEMM);

    zero_kernel<<<32, 256>>>();
    convert_kernel<<<4096, 256>>>(adj);
    sums_kernel<<<128, 256>>>();
    scale_kernel<<<32, 256>>>();
    prep_kernel<<<dim3(512, 2), 256>>>(user, item, W1);
    gemm_kernel<<<dim3(64, 2, 2), 256, SMEM_GEMM>>>();
    final_kernel<<<dim3(512, 2), 256>>>(user, item, W2, out);
}

// round 14
// speedup vs baseline: 1.2505x; 1.0205x over previous
#include <cuda_runtime.h>
#include <cuda_bf16.h>
#include <math.h>
#include <stdint.h>

#define NN 8192
#define DD 64
#define ONES 0x3F803F80u

// ---------------- device scratch (allocation-free) ----------------
__device__ float g_rowsum[NN];
__device__ float g_colsum[NN];
__device__ __align__(16) __nv_bfloat16 g_adjbf[67108864];  // adj bf16 row-major
__device__ __align__(16) __nv_bfloat16 g_Qt[128 * NN];     // Q^T [n][k]
__device__ __align__(16) __nv_bfloat16 g_Pt[128 * NN];     // P^T [n][k]
__device__ __align__(16) float g_RiP[2][NN * 128];         // adj   @ Q split-K partials
__device__ __align__(16) float g_RuP[2][NN * 128];         // adj^T @ P split-K partials

__device__ __forceinline__ uint32_t smem_u32(const void* p) {
    uint32_t a;
    asm("{ .reg .u64 t; cvta.to.shared.u64 t, %1; cvt.u32.u64 %0, t; }" : "=r"(a) : "l"(p));
    return a;
}
__device__ __forceinline__ void cpa16(uint32_t s, const void* g) {
    asm volatile("cp.async.cg.shared.global [%0], [%1], 16;" :: "r"(s), "l"(g) : "memory");
}
__device__ __forceinline__ uint32_t bf2pk(float lo, float hi) {
    __nv_bfloat162 b = __float22bfloat162_rn(make_float2(lo, hi));
    return *(uint32_t*)&b;
}
__device__ __forceinline__ void mma_bf16(float* c, uint32_t a0, uint32_t a1, uint32_t a2,
                                         uint32_t a3, uint32_t b0, uint32_t b1) {
    asm volatile(
        "mma.sync.aligned.m16n8k16.row.col.f32.bf16.bf16.f32 "
        "{%0,%1,%2,%3}, {%4,%5,%6,%7}, {%8,%9}, {%0,%1,%2,%3};"
        : "+f"(c[0]), "+f"(c[1]), "+f"(c[2]), "+f"(c[3])
        : "r"(a0), "r"(a1), "r"(a2), "r"(a3), "r"(b0), "r"(b1));
}

// ---------------- 1) streaming convert fp32 -> bf16 (+ zero colsum) ----------------
__global__ void __launch_bounds__(256) convert_kernel(const float* __restrict__ adj) {
    int gid = blockIdx.x * 256 + threadIdx.x;
    if (gid < NN) g_colsum[gid] = 0.f;  // re-zeroed every replay; consumed by sums_kernel
    const int NF4 = NN * NN / 4;
    const int STR = gridDim.x * 256;
    for (int i = gid; i < NF4; i += STR) {
        float4 v = ((const float4*)adj)[i];
        uint2 o;
        o.x = bf2pk(v.x, v.y);
        o.y = bf2pk(v.z, v.w);
        ((uint2*)g_adjbf)[i] = o;
    }
}

// ---------------- 2) tensor-core row/col sums of adjbf ----------------
#define SROWS 64
#define SCOLS 128
__global__ void __launch_bounds__(256) sums_kernel() {
    __shared__ __align__(16) __nv_bfloat16 st[3][SROWS * SCOLS];
    int tid = threadIdx.x, lane = tid & 31, wid = tid >> 5;
    int r0 = blockIdx.x * SROWS;

    int lr = tid >> 2, lc0 = (tid & 3) * 4;
    const char* gp = (const char*)(g_adjbf + (size_t)(r0 + lr) * NN) + lc0 * 16;
    uint32_t sbase = smem_u32(st);
    uint32_t sto[4];
#pragma unroll
    for (int j = 0; j < 4; j++)
        sto[j] = lr * 256 + (((lc0 + j) ^ (lr & 7)) << 4);

#pragma unroll
    for (int s = 0; s < 2; s++) {
#pragma unroll
        for (int j = 0; j < 4; j++)
            cpa16(sbase + s * (SROWS * SCOLS * 2) + sto[j], gp + (size_t)s * 256 + j * 16);
        asm volatile("cp.async.commit_group;" ::: "memory");
    }

    float rc[4] = {0.f, 0.f, 0.f, 0.f};

    for (int it = 0; it < 64; it++) {
        if (it < 62) asm volatile("cp.async.wait_group 1;" ::: "memory");
        else         asm volatile("cp.async.wait_group 0;" ::: "memory");
        __syncthreads();
        if (it + 2 < 64) {
            int s = (it + 2) % 3;
#pragma unroll
            for (int j = 0; j < 4; j++)
                cpa16(sbase + s * (SROWS * SCOLS * 2) + sto[j],
                      gp + (size_t)(it + 2) * 256 + j * 16);
            asm volatile("cp.async.commit_group;" ::: "memory");
        }
        uint32_t buf = sbase + (it % 3) * (SROWS * SCOLS * 2);

        if (wid < 4) {
            int aRow = wid * 16 + (lane & 15);
            int ax = aRow & 7;
#pragma unroll
            for (int kc = 0; kc < 8; kc++) {
                uint32_t a0, a1, a2, a3;
                uint32_t addr = buf + aRow * 256 + ((((kc << 1) | (lane >> 4)) ^ ax) << 4);
                asm volatile("ldmatrix.sync.aligned.m8n8.x4.shared.b16 {%0,%1,%2,%3}, [%4];"
                             : "=r"(a0), "=r"(a1), "=r"(a2), "=r"(a3) : "r"(addr));
                mma_bf16(rc, a0, a1, a2, a3, ONES, ONES);
            }
        }

        float cc0[4] = {0.f, 0.f, 0.f, 0.f}, cc1[4] = {0.f, 0.f, 0.f, 0.f};
        int srow0 = ((lane >> 4) & 1) * 8 + (lane & 7);
        int sc = wid * 2 + ((lane >> 3) & 1);
#pragma unroll
        for (int kc = 0; kc < 4; kc++) {
            int srow = kc * 16 + srow0;
            uint32_t b0, b1, b2, b3;
            uint32_t addr = buf + srow * 256 + ((sc ^ (srow & 7)) << 4);
            asm volatile("ldmatrix.sync.aligned.m8n8.x4.trans.shared.b16 {%0,%1,%2,%3}, [%4];"
                         : "=r"(b0), "=r"(b1), "=r"(b2), "=r"(b3) : "r"(addr));
            mma_bf16(cc0, ONES, ONES, ONES, ONES, b0, b2);
            mma_bf16(cc1, ONES, ONES, ONES, ONES, b1, b3);
        }
        if (lane < 4) {
            int colb = it * 128 + wid * 16 + 2 * lane;
            atomicAdd(&g_colsum[colb + 0], cc0[0]);
            atomicAdd(&g_colsum[colb + 1], cc0[1]);
            atomicAdd(&g_colsum[colb + 8], cc1[0]);
            atomicAdd(&g_colsum[colb + 9], cc1[1]);
        }
    }

    if (wid < 4 && (lane & 3) == 0) {
        int row = r0 + wid * 16 + (lane >> 2);
        g_rowsum[row] = rc[0];
        g_rowsum[row + 8] = rc[2];
    }
}

// ---------------- 3) build Qt/Pt (bf16, [n][k]); 16 k-rows per block ----------------
__global__ void __launch_bounds__(256) prep_kernel(const float* __restrict__ user,
                                                   const float* __restrict__ item,
                                                   const float* __restrict__ W1) {
    int var = blockIdx.y;  // 0 -> Pt (src=item, scale=rsqrt(rowsum)), 1 -> Qt
    const float* src = var ? user : item;
    const float* pas = var ? item : user;
    const float* sums = var ? g_colsum : g_rowsum;
    __nv_bfloat16* out = var ? g_Qt : g_Pt;

    __shared__ __align__(16) float Ws[DD * DD];
    __shared__ float Xs[16 * DD];
    __shared__ __nv_bfloat16 T[128 * 18];
    int tid = threadIdx.x;
    for (int i = tid; i < DD * DD; i += 256) Ws[i] = W1[i];
    int k0 = blockIdx.x * 16;
    for (int i = tid; i < 16 * DD; i += 256) Xs[i] = src[k0 * DD + i];
    __syncthreads();

    int row = tid >> 4;
    int g4 = (tid & 15) * 4;
    float a0 = 0.f, a1 = 0.f, a2 = 0.f, a3 = 0.f;
#pragma unroll 8
    for (int k = 0; k < DD; k++) {
        float x = Xs[row * DD + k];
        float4 w = *(const float4*)&Ws[k * DD + g4];
        a0 += x * w.x; a1 += x * w.y; a2 += x * w.z; a3 += x * w.w;
    }
    int gr = k0 + row;
    float s = rsqrtf(sums[gr]);
    T[(g4 + 0) * 18 + row] = __float2bfloat16(s * a0);
    T[(g4 + 1) * 18 + row] = __float2bfloat16(s * a1);
    T[(g4 + 2) * 18 + row] = __float2bfloat16(s * a2);
    T[(g4 + 3) * 18 + row] = __float2bfloat16(s * a3);
    const float* p = pas + gr * DD;
#pragma unroll
    for (int j = 0; j < 4; j++)
        T[(64 + g4 + j) * 18 + row] = __float2bfloat16(s * p[g4 + j]);
    __syncthreads();

    if (tid < 128) {
        int n = tid;
        __align__(16) __nv_bfloat16 v[16];
#pragma unroll
        for (int k = 0; k < 16; k++) v[k] = T[n * 18 + k];
        uint4* dst = (uint4*)(out + (size_t)n * NN + k0);
        dst[0] = ((uint4*)v)[0];
        dst[1] = ((uint4*)v)[1];
    }
}

// ---------------- 4) GEMMs: split-K=2, ping-pong pipeline, occupancy 2 (R11 proven) ----
// grid (64, 2, 2); z = K-half. Tile 128x128, BK=64.
//  y=0: RiP[z][m-tile][128] = adjbf[m-tile][Khalf] @ Qt[:, Khalf]
//  y=1: RuT partial = Pt[:, Khalf] @ adjbf[Khalf][n-tile] -> transpose -> g_RuP[z][n][m]
#define NST 2
#define ASTG 16384
#define NITER2 64
#define SMEM_GEMM 67584   // >= max(2*NST*ASTG=64KB, transpose 128*132*4=67584)

__global__ void __launch_bounds__(256, 2) gemm_kernel() {
    extern __shared__ char sm[];
    uint32_t sA = smem_u32(sm);
    uint32_t sB = sA + NST * ASTG;

    int tid = threadIdx.x;
    int lane = tid & 31, wid = tid >> 5;
    int warpM = wid & 3, warpN = wid >> 2;  // 4x2 warps, warp tile 32m x 64n
    int z = blockIdx.z;
    size_t kbase = (size_t)z * 4096;        // K-half offset in elements

    float c[2][8][4];
#pragma unroll
    for (int f = 0; f < 2; f++)
#pragma unroll
        for (int n = 0; n < 8; n++)
#pragma unroll
            for (int j = 0; j < 4; j++) c[f][n][j] = 0.f;

    if (blockIdx.y == 0) {
        // ---------------- GEMM1: RiP[z] = adjbf @ Qt (K-half) ----------------
        int m0 = blockIdx.x * 128;
        float* Cg = g_RiP[z];
        int lr = tid >> 1, lc0 = (tid & 1) * 4;
        const char* gAp = (const char*)(g_adjbf + (size_t)(m0 + lr) * NN + kbase) + lc0 * 16;
        const char* gBp = (const char*)(g_Qt + (size_t)lr * NN + kbase) + lc0 * 16;
        uint32_t sto[4];
#pragma unroll
        for (int j = 0; j < 4; j++)
            sto[j] = lr * 128 + (((lc0 + j) ^ (lr & 7)) << 4);

        int aRow[2], aX[2];
#pragma unroll
        for (int f = 0; f < 2; f++) {
            aRow[f] = warpM * 32 + f * 16 + (lane & 15);
            aX[f] = aRow[f] & 7;
        }
        int ah = lane >> 4;
        int bRow[4], bX[4];
#pragma unroll
        for (int g = 0; g < 4; g++) {
            bRow[g] = warpN * 64 + g * 16 + (lane >> 4) * 8 + (lane & 7);
            bX[g] = bRow[g] & 7;
        }
        int bh = (lane >> 3) & 1;

        // prologue: stage 0
#pragma unroll
        for (int j = 0; j < 4; j++) {
            cpa16(sA + sto[j], gAp + j * 16);
            cpa16(sB + sto[j], gBp + j * 16);
        }
        asm volatile("cp.async.commit_group;" ::: "memory");

        for (int it = 0; it < NITER2; it++) {
            asm volatile("cp.async.wait_group 0;" ::: "memory");
            __syncthreads();
            if (it + 1 < NITER2) {
                int s = (it + 1) & 1;
                size_t kb = (size_t)(it + 1) * 128;
#pragma unroll
                for (int j = 0; j < 4; j++) {
                    cpa16(sA + s * ASTG + sto[j], gAp + kb + j * 16);
                    cpa16(sB + s * ASTG + sto[j], gBp + kb + j * 16);
                }
                asm volatile("cp.async.commit_group;" ::: "memory");
            }
            uint32_t ba = sA + (it & 1) * ASTG;
            uint32_t bb = sB + (it & 1) * ASTG;
#pragma unroll
            for (int ks = 0; ks < 4; ks++) {
                uint32_t am[2][4], bn[4][4];
#pragma unroll
                for (int f = 0; f < 2; f++) {
                    uint32_t addr = ba + aRow[f] * 128 + ((((ks << 1) | ah) ^ aX[f]) << 4);
                    asm volatile("ldmatrix.sync.aligned.m8n8.x4.shared.b16 {%0,%1,%2,%3}, [%4];"
                                 : "=r"(am[f][0]), "=r"(am[f][1]), "=r"(am[f][2]), "=r"(am[f][3])
                                 : "r"(addr));
                }
#pragma unroll
                for (int g = 0; g < 4; g++) {
                    uint32_t addr = bb + bRow[g] * 128 + ((((ks << 1) | bh) ^ bX[g]) << 4);
                    asm volatile("ldmatrix.sync.aligned.m8n8.x4.shared.b16 {%0,%1,%2,%3}, [%4];"
                                 : "=r"(bn[g][0]), "=r"(bn[g][1]), "=r"(bn[g][2]), "=r"(bn[g][3])
                                 : "r"(addr));
                }
#pragma unroll
                for (int f = 0; f < 2; f++)
#pragma unroll
                    for (int g = 0; g < 4; g++) {
                        mma_bf16(c[f][g * 2], am[f][0], am[f][1], am[f][2], am[f][3],
                                 bn[g][0], bn[g][1]);
                        mma_bf16(c[f][g * 2 + 1], am[f][0], am[f][1], am[f][2], am[f][3],
                                 bn[g][2], bn[g][3]);
                    }
            }
        }
#pragma unroll
        for (int f = 0; f < 2; f++) {
            int row = m0 + warpM * 32 + f * 16 + (lane >> 2);
#pragma unroll
            for (int n = 0; n < 8; n++) {
                int col = warpN * 64 + n * 8 + (lane & 3) * 2;
                *(float2*)&Cg[(size_t)row * 128 + col] = make_float2(c[f][n][0], c[f][n][1]);
                *(float2*)&Cg[(size_t)(row + 8) * 128 + col] = make_float2(c[f][n][2], c[f][n][3]);
            }
        }
    } else {
        // ---------------- GEMM2: RuT partial = Pt @ adjbf[Khalf, n-tile] ----------------
        int n0 = blockIdx.x * 128;
        float* Cg = g_RuP[z];
        int lrA = tid >> 1, lcA = (tid & 1) * 4;
        const char* gAp = (const char*)(g_Pt + (size_t)lrA * NN + kbase) + lcA * 16;
        uint32_t stoA[4];
#pragma unroll
        for (int j = 0; j < 4; j++)
            stoA[j] = lrA * 128 + (((lcA + j) ^ (lrA & 7)) << 4);

        int lrB = tid >> 2, lcB = (tid & 3) * 4;
        const char* gBp = (const char*)(g_adjbf + (size_t)(kbase + lrB) * NN + n0) + lcB * 16;
        uint32_t stoB[4];
#pragma unroll
        for (int j = 0; j < 4; j++)
            stoB[j] = lrB * 256 + (((lcB + j) ^ (lrB & 7)) << 4);

        int aRow[2], aX[2];
#pragma unroll
        for (int f = 0; f < 2; f++) {
            aRow[f] = warpM * 32 + f * 16 + (lane & 15);
            aX[f] = aRow[f] & 7;
        }
        int ah = lane >> 4;
        int srow0 = ((lane >> 4) & 1) * 8 + (lane & 7);
        int scb = (lane >> 3) & 1;

        // prologue: stage 0
#pragma unroll
        for (int j = 0; j < 4; j++) {
            cpa16(sA + stoA[j], gAp + j * 16);
            cpa16(sB + stoB[j], gBp + j * 16);
        }
        asm volatile("cp.async.commit_group;" ::: "memory");

        for (int it = 0; it < NITER2; it++) {
            asm volatile("cp.async.wait_group 0;" ::: "memory");
            __syncthreads();
            if (it + 1 < NITER2) {
                int s = (it + 1) & 1;
                size_t kit = (size_t)(it + 1);
#pragma unroll
                for (int j = 0; j < 4; j++) {
                    cpa16(sA + s * ASTG + stoA[j], gAp + kit * 128 + j * 16);
                    cpa16(sB + s * ASTG + stoB[j], gBp + kit * 64 * NN * 2 + j * 16);
                }
                asm volatile("cp.async.commit_group;" ::: "memory");
            }
            uint32_t ba = sA + (it & 1) * ASTG;
            uint32_t bb = sB + (it & 1) * ASTG;
#pragma unroll
            for (int ks = 0; ks < 4; ks++) {
                uint32_t am[2][4], bn[4][4];
#pragma unroll
                for (int f = 0; f < 2; f++) {
                    uint32_t addr = ba + aRow[f] * 128 + ((((ks << 1) | ah) ^ aX[f]) << 4);
                    asm volatile("ldmatrix.sync.aligned.m8n8.x4.shared.b16 {%0,%1,%2,%3}, [%4];"
                                 : "=r"(am[f][0]), "=r"(am[f][1]), "=r"(am[f][2]), "=r"(am[f][3])
                                 : "r"(addr));
                }
                int srow = ks * 16 + srow0;
                int sxr = srow & 7;
#pragma unroll
                for (int g = 0; g < 4; g++) {
                    int sc = warpN * 8 + g * 2 + scb;
                    uint32_t addr = bb + srow * 256 + ((sc ^ sxr) << 4);
                    asm volatile("ldmatrix.sync.aligned.m8n8.x4.trans.shared.b16 {%0,%1,%2,%3}, [%4];"
                                 : "=r"(bn[g][0]), "=r"(bn[g][1]), "=r"(bn[g][2]), "=r"(bn[g][3])
                                 : "r"(addr));
                }
#pragma unroll
                for (int f = 0; f < 2; f++)
#pragma unroll
                    for (int g = 0; g < 4; g++) {
                        mma_bf16(c[f][g * 2], am[f][0], am[f][1], am[f][2], am[f][3],
                                 bn[g][0], bn[g][2]);
                        mma_bf16(c[f][g * 2 + 1], am[f][0], am[f][1], am[f][2], am[f][3],
                                 bn[g][1], bn[g][3]);
                    }
            }
        }

        // transpose epilogue: smem [128n][132] fp32, then coalesced rows of partial Ru
        __syncthreads();
        float* tr = (float*)sm;
#pragma unroll
        for (int f = 0; f < 2; f++) {
            int m = warpM * 32 + f * 16 + (lane >> 2);
#pragma unroll
            for (int n = 0; n < 8; n++) {
                int nc = warpN * 64 + n * 8 + (lane & 3) * 2;
                tr[nc * 132 + m] = c[f][n][0];
                tr[(nc + 1) * 132 + m] = c[f][n][1];
                tr[nc * 132 + m + 8] = c[f][n][2];
                tr[(nc + 1) * 132 + m + 8] = c[f][n][3];
            }
        }
        __syncthreads();
        for (int i = tid; i < 128 * 32; i += 256) {
            int r = i >> 5, q = i & 31;
            float4 v = *(float4*)&tr[r * 132 + q * 4];
            *(float4*)&Cg[(size_t)(n0 + r) * 128 + q * 4] = v;
        }
    }
}

// ---------------- 5) epilogue (sums split-K partials, inline rsqrt) ----------------
__global__ void __launch_bounds__(256) final_kernel(const float* __restrict__ user,
                                                    const float* __restrict__ item,
                                                    const float* __restrict__ W2,
                                                    float* __restrict__ out) {
    int var = blockIdx.y;  // 0 -> updated_user (Ru, rsqrt(colsum)), 1 -> updated_item
    const float* R0 = var ? g_RiP[0] : g_RuP[0];
    const float* R1 = var ? g_RiP[1] : g_RuP[1];
    const float* sums = var ? g_rowsum : g_colsum;
    const float* src = var ? user : item;
    const float* tgt = var ? item : user;
    float* o = out + (size_t)var * NN * DD;

    __shared__ __align__(16) float Ws[DD * DD];
    __shared__ float Hs[16 * DD];
    int tid = threadIdx.x;
    for (int i = tid; i < DD * DD; i += 256) Ws[i] = W2[i];

    int r0 = blockIdx.x * 16;
    int row = tid >> 4;
    int cg = (tid & 15) * 4;
    int gr = r0 + row;
    float s = rsqrtf(sums[gr]);
#pragma unroll
    for (int j = 0; j < 4; j++) {
        float rv = R0[gr * 128 + 64 + cg + j] + R1[gr * 128 + 64 + cg + j];
        Hs[row * DD + cg + j] = src[gr * DD + cg + j] * (s * rv);
    }
    __syncthreads();

    float acc[4] = {0.f, 0.f, 0.f, 0.f};
#pragma unroll 8
    for (int k = 0; k < DD; k++) {
        float hh = Hs[row * DD + k];
        float4 w = *(const float4*)&Ws[k * DD + cg];
        acc[0] += hh * w.x; acc[1] += hh * w.y; acc[2] += hh * w.z; acc[3] += hh * w.w;
    }
#pragma unroll
    for (int j = 0; j < 4; j++) {
        float rv = R0[gr * 128 + cg + j] + R1[gr * 128 + cg + j];
        float x = s * rv + acc[j] + tgt[gr * DD + cg + j];
        o[gr * DD + cg + j] = x > 0.f ? x : 0.2f * x;
    }
}

// ---------------- launch ----------------
extern "C" void kernel_launch(void* const* d_in, const int* in_sizes, int n_in,
                              void* d_out, int out_size) {
    const float* user = (const float*)d_in[0];
    const float* item = (const float*)d_in[1];
    const float* adj  = (const float*)d_in[2];
    const float* W1   = (const float*)d_in[3];
    const float* W2   = (const float*)d_in[4];
    float* out = (float*)d_out;

    cudaFuncSetAttribute(gemm_kernel, cudaFuncAttributeMaxDynamicSharedMemorySize, SMEM_GEMM);

    convert_kernel<<<4096, 256>>>(adj);
    sums_kernel<<<128, 256>>>();
    prep_kernel<<<dim3(512, 2), 256>>>(user, item, W1);
    gemm_kernel<<<dim3(64, 2, 2), 256, SMEM_GEMM>>>();
    final_kernel<<<dim3(512, 2), 256>>>(user, item, W2, out);
}